// round 1
// baseline (speedup 1.0000x reference)
#include <cuda_runtime.h>

#define D 128
#define BM 64
#define BK 32
#define SA_LD 40   // padded lda for sA to break STS.128 bank conflicts

// Scratch (allocation-free): 50000*128 floats each = 25.6 MB
__device__ float g_H[50000 * 128];
__device__ float g_AGG[50000 * 128];

__global__ void __launch_bounds__(256) zero_kernel(float* __restrict__ p, int n4) {
    int i = blockIdx.x * blockDim.x + threadIdx.x;
    float4 z = make_float4(0.f, 0.f, 0.f, 0.f);
    for (; i < n4; i += gridDim.x * blockDim.x)
        ((float4*)p)[i] = z;
}

// One warp per edge: gather 128 floats of H[src] (float4/lane), scatter-add into AGG[dst].
__global__ void __launch_bounds__(256) scatter_kernel(
    const float* __restrict__ H, const int* __restrict__ src,
    const int* __restrict__ dst, float* __restrict__ AGG, int E)
{
    int w = (blockIdx.x * blockDim.x + threadIdx.x) >> 5;
    int lane = threadIdx.x & 31;
    if (w >= E) return;
    int s = __ldg(src + w);
    int d = __ldg(dst + w);
    float4 v = __ldg((const float4*)(H + (size_t)s * D) + lane);
    float* o = AGG + (size_t)d * D + lane * 4;
    atomicAdd(o + 0, v.x);
    atomicAdd(o + 1, v.y);
    atomicAdd(o + 2, v.z);
    atomicAdd(o + 3, v.w);
}

// One K-pass of C += A[rows, 0:128] @ W[0:128, 0:128] accumulated into acc[8][4].
__device__ __forceinline__ void mm_pass(
    const float* __restrict__ A, const float* __restrict__ W,
    int row0, int N, float (*sA)[SA_LD], float (*sW)[D],
    float acc[8][4], int tid, int tx, int ty)
{
    for (int k0 = 0; k0 < D; k0 += BK) {
        // load A tile: BM x BK = 512 float4, 2 per thread
        #pragma unroll
        for (int i = 0; i < 2; i++) {
            int s = tid + i * 256;
            int r = s >> 3, kq = s & 7;
            float4 v = make_float4(0.f, 0.f, 0.f, 0.f);
            int gr = row0 + r;
            if (gr < N) v = *(const float4*)(A + (size_t)gr * D + k0 + kq * 4);
            *(float4*)&sA[r][kq * 4] = v;
        }
        // load W tile: BK x 128 = 1024 float4, 4 per thread
        #pragma unroll
        for (int i = 0; i < 4; i++) {
            int s = tid + i * 256;
            int r = s >> 5, cq = s & 31;
            *(float4*)&sW[r][cq * 4] = *(const float4*)(W + (size_t)(k0 + r) * D + cq * 4);
        }
        __syncthreads();
        #pragma unroll
        for (int k = 0; k < BK; k++) {
            float4 wv = *(const float4*)&sW[k][tx * 4];
            #pragma unroll
            for (int r = 0; r < 8; r++) {
                float a = sA[ty * 8 + r][k];   // broadcast within warp
                acc[r][0] += a * wv.x;
                acc[r][1] += a * wv.y;
                acc[r][2] += a * wv.z;
                acc[r][3] += a * wv.w;
            }
        }
        __syncthreads();
    }
}

// DUAL=false: out = A1@W1 + bias                      (in_fc)
// DUAL=true : out = relu(A1@W1 + A2@W2 + bias) + Hres (GraphConv layer, in-place safe)
template <bool DUAL>
__global__ void __launch_bounds__(256) gemm_kernel(
    const float* __restrict__ A1, const float* __restrict__ W1,
    const float* __restrict__ A2, const float* __restrict__ W2,
    const float* __restrict__ bias, const float* __restrict__ Hres,
    float* __restrict__ out, int N)
{
    __shared__ float sA[BM][SA_LD];
    __shared__ float sW[BK][D];
    int tid = threadIdx.x;
    int tx = tid & 31;   // col group -> cols tx*4 .. tx*4+3
    int ty = tid >> 5;   // row group -> rows ty*8 .. ty*8+7
    int row0 = blockIdx.x * BM;

    float acc[8][4];
    #pragma unroll
    for (int r = 0; r < 8; r++)
        #pragma unroll
        for (int c = 0; c < 4; c++) acc[r][c] = 0.f;

    mm_pass(A1, W1, row0, N, sA, sW, acc, tid, tx, ty);
    if (DUAL) mm_pass(A2, W2, row0, N, sA, sW, acc, tid, tx, ty);

    float4 b4 = *(const float4*)(bias + tx * 4);
    #pragma unroll
    for (int r = 0; r < 8; r++) {
        int gr = row0 + ty * 8 + r;
        if (gr >= N) continue;
        float4 o;
        o.x = acc[r][0] + b4.x;
        o.y = acc[r][1] + b4.y;
        o.z = acc[r][2] + b4.z;
        o.w = acc[r][3] + b4.w;
        if (DUAL) {
            float4 h4 = *(const float4*)(Hres + (size_t)gr * D + tx * 4);
            o.x = fmaxf(o.x, 0.f) + h4.x;
            o.y = fmaxf(o.y, 0.f) + h4.y;
            o.z = fmaxf(o.z, 0.f) + h4.z;
            o.w = fmaxf(o.w, 0.f) + h4.w;
        }
        *(float4*)(out + (size_t)gr * D + tx * 4) = o;
    }
}

extern "C" void kernel_launch(void* const* d_in, const int* in_sizes, int n_in,
                              void* d_out, int out_size)
{
    const float* x       = (const float*)d_in[0];
    const int*   ei      = (const int*)  d_in[1];
    const float* in_fc_w = (const float*)d_in[2];
    const float* in_fc_b = (const float*)d_in[3];
    const float* w_rel   = (const float*)d_in[4];
    const float* b_rel   = (const float*)d_in[5];
    const float* w_root  = (const float*)d_in[6];

    int N = in_sizes[0] / D;
    int E = in_sizes[1] / 2;
    const int* src = ei;
    const int* dst = ei + E;

    float *H, *AGG;
    cudaGetSymbolAddress((void**)&H,   g_H);
    cudaGetSymbolAddress((void**)&AGG, g_AGG);

    int gblocks = (N + BM - 1) / BM;
    int sblocks = (E * 32 + 255) / 256;

    // h = x @ in_fc_w + in_fc_b
    gemm_kernel<false><<<gblocks, 256>>>(x, in_fc_w, nullptr, nullptr,
                                         in_fc_b, nullptr, H, N);

    for (int l = 0; l < 3; l++) {
        zero_kernel<<<1024, 256>>>(AGG, N * D / 4);
        scatter_kernel<<<sblocks, 256>>>(H, src, dst, AGG, E);
        float* out_l = (l == 2) ? (float*)d_out : H;
        gemm_kernel<true><<<gblocks, 256>>>(AGG, w_rel + (size_t)l * D * D,
                                            H,   w_root + (size_t)l * D * D,
                                            b_rel + (size_t)l * D,
                                            H, out_l, N);
    }
}

// round 2
// speedup vs baseline: 1.0006x; 1.0006x over previous
#include <cuda_runtime.h>

#define D 128
#define BM 64
#define BK 32
#define SA_LD 40   // padded lda for sA to break STS.128 bank conflicts

// Scratch (allocation-free): 50000*128 floats each = 25.6 MB
__device__ float g_H[50000 * 128];
__device__ float g_AGG[50000 * 128];

__global__ void __launch_bounds__(256) zero_kernel(float* __restrict__ p, int n4) {
    int i = blockIdx.x * blockDim.x + threadIdx.x;
    float4 z = make_float4(0.f, 0.f, 0.f, 0.f);
    for (; i < n4; i += gridDim.x * blockDim.x)
        ((float4*)p)[i] = z;
}

// One warp per edge: gather 128 floats of H[src] (float4/lane), scatter-add into AGG[dst].
__global__ void __launch_bounds__(256) scatter_kernel(
    const float* __restrict__ H, const int* __restrict__ src,
    const int* __restrict__ dst, float* __restrict__ AGG, int E)
{
    int w = (blockIdx.x * blockDim.x + threadIdx.x) >> 5;
    int lane = threadIdx.x & 31;
    if (w >= E) return;
    int s = __ldg(src + w);
    int d = __ldg(dst + w);
    float4 v = __ldg((const float4*)(H + (size_t)s * D) + lane);
    float* o = AGG + (size_t)d * D + lane * 4;
    atomicAdd(o + 0, v.x);
    atomicAdd(o + 1, v.y);
    atomicAdd(o + 2, v.z);
    atomicAdd(o + 3, v.w);
}

// One K-pass of C += A[rows, 0:128] @ W[0:128, 0:128] accumulated into acc[8][4].
__device__ __forceinline__ void mm_pass(
    const float* __restrict__ A, const float* __restrict__ W,
    int row0, int N, float (*sA)[SA_LD], float (*sW)[D],
    float acc[8][4], int tid, int tx, int ty)
{
    for (int k0 = 0; k0 < D; k0 += BK) {
        // load A tile: BM x BK = 512 float4, 2 per thread
        #pragma unroll
        for (int i = 0; i < 2; i++) {
            int s = tid + i * 256;
            int r = s >> 3, kq = s & 7;
            float4 v = make_float4(0.f, 0.f, 0.f, 0.f);
            int gr = row0 + r;
            if (gr < N) v = *(const float4*)(A + (size_t)gr * D + k0 + kq * 4);
            *(float4*)&sA[r][kq * 4] = v;
        }
        // load W tile: BK x 128 = 1024 float4, 4 per thread
        #pragma unroll
        for (int i = 0; i < 4; i++) {
            int s = tid + i * 256;
            int r = s >> 5, cq = s & 31;
            *(float4*)&sW[r][cq * 4] = *(const float4*)(W + (size_t)(k0 + r) * D + cq * 4);
        }
        __syncthreads();
        #pragma unroll
        for (int k = 0; k < BK; k++) {
            float4 wv = *(const float4*)&sW[k][tx * 4];
            #pragma unroll
            for (int r = 0; r < 8; r++) {
                float a = sA[ty * 8 + r][k];   // broadcast within warp
                acc[r][0] += a * wv.x;
                acc[r][1] += a * wv.y;
                acc[r][2] += a * wv.z;
                acc[r][3] += a * wv.w;
            }
        }
        __syncthreads();
    }
}

// DUAL=false: out = A1@W1 + bias                      (in_fc)
// DUAL=true : out = relu(A1@W1 + A2@W2 + bias) + Hres (GraphConv layer, in-place safe)
template <bool DUAL>
__global__ void __launch_bounds__(256) gemm_kernel(
    const float* __restrict__ A1, const float* __restrict__ W1,
    const float* __restrict__ A2, const float* __restrict__ W2,
    const float* __restrict__ bias, const float* __restrict__ Hres,
    float* __restrict__ out, int N)
{
    __shared__ float sA[BM][SA_LD];
    __shared__ float sW[BK][D];
    int tid = threadIdx.x;
    int tx = tid & 31;   // col group -> cols tx*4 .. tx*4+3
    int ty = tid >> 5;   // row group -> rows ty*8 .. ty*8+7
    int row0 = blockIdx.x * BM;

    float acc[8][4];
    #pragma unroll
    for (int r = 0; r < 8; r++)
        #pragma unroll
        for (int c = 0; c < 4; c++) acc[r][c] = 0.f;

    mm_pass(A1, W1, row0, N, sA, sW, acc, tid, tx, ty);
    if (DUAL) mm_pass(A2, W2, row0, N, sA, sW, acc, tid, tx, ty);

    float4 b4 = *(const float4*)(bias + tx * 4);
    #pragma unroll
    for (int r = 0; r < 8; r++) {
        int gr = row0 + ty * 8 + r;
        if (gr >= N) continue;
        float4 o;
        o.x = acc[r][0] + b4.x;
        o.y = acc[r][1] + b4.y;
        o.z = acc[r][2] + b4.z;
        o.w = acc[r][3] + b4.w;
        if (DUAL) {
            float4 h4 = *(const float4*)(Hres + (size_t)gr * D + tx * 4);
            o.x = fmaxf(o.x, 0.f) + h4.x;
            o.y = fmaxf(o.y, 0.f) + h4.y;
            o.z = fmaxf(o.z, 0.f) + h4.z;
            o.w = fmaxf(o.w, 0.f) + h4.w;
        }
        *(float4*)(out + (size_t)gr * D + tx * 4) = o;
    }
}

extern "C" void kernel_launch(void* const* d_in, const int* in_sizes, int n_in,
                              void* d_out, int out_size)
{
    const float* x       = (const float*)d_in[0];
    const int*   ei      = (const int*)  d_in[1];
    const float* in_fc_w = (const float*)d_in[2];
    const float* in_fc_b = (const float*)d_in[3];
    const float* w_rel   = (const float*)d_in[4];
    const float* b_rel   = (const float*)d_in[5];
    const float* w_root  = (const float*)d_in[6];

    int N = in_sizes[0] / D;
    int E = in_sizes[1] / 2;
    const int* src = ei;
    const int* dst = ei + E;

    float *H, *AGG;
    cudaGetSymbolAddress((void**)&H,   g_H);
    cudaGetSymbolAddress((void**)&AGG, g_AGG);

    int gblocks = (N + BM - 1) / BM;
    int sblocks = (E * 32 + 255) / 256;

    // h = x @ in_fc_w + in_fc_b
    gemm_kernel<false><<<gblocks, 256>>>(x, in_fc_w, nullptr, nullptr,
                                         in_fc_b, nullptr, H, N);

    for (int l = 0; l < 3; l++) {
        zero_kernel<<<1024, 256>>>(AGG, N * D / 4);
        scatter_kernel<<<sblocks, 256>>>(H, src, dst, AGG, E);
        float* out_l = (l == 2) ? (float*)d_out : H;
        gemm_kernel<true><<<gblocks, 256>>>(AGG, w_rel + (size_t)l * D * D,
                                            H,   w_root + (size_t)l * D * D,
                                            b_rel + (size_t)l * D,
                                            H, out_l, N);
    }
}

// round 3
// speedup vs baseline: 2.0330x; 2.0318x over previous
#include <cuda_runtime.h>

#define D 128
#define BM 64
#define BK 32
#define SA_LD 40   // padded lda for sA to break STS.128 bank conflicts

#define MAXN 50000
#define MAXE 800000

// Scratch (allocation-free)
__device__ float g_H[MAXN * D];
__device__ float g_AGG[MAXN * D];
__device__ int   g_cnt[MAXN];
__device__ int   g_row_ptr[MAXN + 1];
__device__ int   g_cursor[MAXN];
__device__ int   g_adj[MAXE];

// ---------------- CSR build ----------------

__global__ void __launch_bounds__(256) zero_int_kernel(int* __restrict__ p, int n) {
    int i = blockIdx.x * blockDim.x + threadIdx.x;
    for (; i < n; i += gridDim.x * blockDim.x) p[i] = 0;
}

__global__ void __launch_bounds__(256) hist_kernel(
    const int* __restrict__ dst, int* __restrict__ cnt, int E)
{
    int i = blockIdx.x * blockDim.x + threadIdx.x;
    for (; i < E; i += gridDim.x * blockDim.x)
        atomicAdd(&cnt[dst[i]], 1);
}

// Single-block exclusive scan over n counters -> row_ptr[0..n], cursor copy.
__global__ void __launch_bounds__(1024) scan_kernel(
    const int* __restrict__ cnt, int* __restrict__ row_ptr,
    int* __restrict__ cursor, int n)
{
    __shared__ int warp_sums[32];
    int tid = threadIdx.x;
    int chunk = (n + 1023) / 1024;
    int beg = tid * chunk;
    int end = min(beg + chunk, n);

    int local = 0;
    for (int i = beg; i < end; i++) local += cnt[i];

    int lane = tid & 31, w = tid >> 5;
    int v = local;
    #pragma unroll
    for (int o = 1; o < 32; o <<= 1) {
        int t = __shfl_up_sync(~0u, v, o);
        if (lane >= o) v += t;
    }
    if (lane == 31) warp_sums[w] = v;
    __syncthreads();
    if (w == 0) {
        int s = warp_sums[lane];
        #pragma unroll
        for (int o = 1; o < 32; o <<= 1) {
            int t = __shfl_up_sync(~0u, s, o);
            if (lane >= o) s += t;
        }
        warp_sums[lane] = s;
    }
    __syncthreads();

    int excl = v - local + (w > 0 ? warp_sums[w - 1] : 0);
    int run = excl;
    for (int i = beg; i < end; i++) {
        row_ptr[i] = run;
        cursor[i]  = run;
        run += cnt[i];
    }
    if (tid == 1023) row_ptr[n] = run;
}

__global__ void __launch_bounds__(256) fill_kernel(
    const int* __restrict__ src, const int* __restrict__ dst,
    int* __restrict__ cursor, int* __restrict__ adj, int E)
{
    int i = blockIdx.x * blockDim.x + threadIdx.x;
    for (; i < E; i += gridDim.x * blockDim.x) {
        int p = atomicAdd(&cursor[dst[i]], 1);
        adj[p] = src[i];
    }
}

// ---------------- gather-aggregate (no atomics) ----------------

__global__ void __launch_bounds__(256) aggregate_kernel(
    const float* __restrict__ H, const int* __restrict__ row_ptr,
    const int* __restrict__ adj, float* __restrict__ AGG, int N)
{
    int node = (blockIdx.x * blockDim.x + threadIdx.x) >> 5;
    int lane = threadIdx.x & 31;
    if (node >= N) return;
    int beg = __ldg(row_ptr + node);
    int end = __ldg(row_ptr + node + 1);

    float4 acc = make_float4(0.f, 0.f, 0.f, 0.f);
    int e = beg;
    // unroll by 4 for MLP
    for (; e + 4 <= end; e += 4) {
        int s0 = __ldg(adj + e + 0);
        int s1 = __ldg(adj + e + 1);
        int s2 = __ldg(adj + e + 2);
        int s3 = __ldg(adj + e + 3);
        float4 v0 = __ldg((const float4*)(H + (size_t)s0 * D) + lane);
        float4 v1 = __ldg((const float4*)(H + (size_t)s1 * D) + lane);
        float4 v2 = __ldg((const float4*)(H + (size_t)s2 * D) + lane);
        float4 v3 = __ldg((const float4*)(H + (size_t)s3 * D) + lane);
        acc.x += v0.x + v1.x + v2.x + v3.x;
        acc.y += v0.y + v1.y + v2.y + v3.y;
        acc.z += v0.z + v1.z + v2.z + v3.z;
        acc.w += v0.w + v1.w + v2.w + v3.w;
    }
    for (; e < end; e++) {
        int s = __ldg(adj + e);
        float4 v = __ldg((const float4*)(H + (size_t)s * D) + lane);
        acc.x += v.x; acc.y += v.y; acc.z += v.z; acc.w += v.w;
    }
    *((float4*)(AGG + (size_t)node * D) + lane) = acc;
}

// ---------------- GEMM (fp32 SIMT, at FFMA ceiling) ----------------

__device__ __forceinline__ void mm_pass(
    const float* __restrict__ A, const float* __restrict__ W,
    int row0, int N, float (*sA)[SA_LD], float (*sW)[D],
    float acc[8][4], int tid, int tx, int ty)
{
    for (int k0 = 0; k0 < D; k0 += BK) {
        #pragma unroll
        for (int i = 0; i < 2; i++) {
            int s = tid + i * 256;
            int r = s >> 3, kq = s & 7;
            float4 v = make_float4(0.f, 0.f, 0.f, 0.f);
            int gr = row0 + r;
            if (gr < N) v = *(const float4*)(A + (size_t)gr * D + k0 + kq * 4);
            *(float4*)&sA[r][kq * 4] = v;
        }
        #pragma unroll
        for (int i = 0; i < 4; i++) {
            int s = tid + i * 256;
            int r = s >> 5, cq = s & 31;
            *(float4*)&sW[r][cq * 4] = *(const float4*)(W + (size_t)(k0 + r) * D + cq * 4);
        }
        __syncthreads();
        #pragma unroll
        for (int k = 0; k < BK; k++) {
            float4 wv = *(const float4*)&sW[k][tx * 4];
            #pragma unroll
            for (int r = 0; r < 8; r++) {
                float a = sA[ty * 8 + r][k];
                acc[r][0] += a * wv.x;
                acc[r][1] += a * wv.y;
                acc[r][2] += a * wv.z;
                acc[r][3] += a * wv.w;
            }
        }
        __syncthreads();
    }
}

template <bool DUAL>
__global__ void __launch_bounds__(256) gemm_kernel(
    const float* __restrict__ A1, const float* __restrict__ W1,
    const float* __restrict__ A2, const float* __restrict__ W2,
    const float* __restrict__ bias, const float* __restrict__ Hres,
    float* __restrict__ out, int N)
{
    __shared__ float sA[BM][SA_LD];
    __shared__ float sW[BK][D];
    int tid = threadIdx.x;
    int tx = tid & 31;
    int ty = tid >> 5;
    int row0 = blockIdx.x * BM;

    float acc[8][4];
    #pragma unroll
    for (int r = 0; r < 8; r++)
        #pragma unroll
        for (int c = 0; c < 4; c++) acc[r][c] = 0.f;

    mm_pass(A1, W1, row0, N, sA, sW, acc, tid, tx, ty);
    if (DUAL) mm_pass(A2, W2, row0, N, sA, sW, acc, tid, tx, ty);

    float4 b4 = *(const float4*)(bias + tx * 4);
    #pragma unroll
    for (int r = 0; r < 8; r++) {
        int gr = row0 + ty * 8 + r;
        if (gr >= N) continue;
        float4 o;
        o.x = acc[r][0] + b4.x;
        o.y = acc[r][1] + b4.y;
        o.z = acc[r][2] + b4.z;
        o.w = acc[r][3] + b4.w;
        if (DUAL) {
            float4 h4 = *(const float4*)(Hres + (size_t)gr * D + tx * 4);
            o.x = fmaxf(o.x, 0.f) + h4.x;
            o.y = fmaxf(o.y, 0.f) + h4.y;
            o.z = fmaxf(o.z, 0.f) + h4.z;
            o.w = fmaxf(o.w, 0.f) + h4.w;
        }
        *(float4*)(out + (size_t)gr * D + tx * 4) = o;
    }
}

extern "C" void kernel_launch(void* const* d_in, const int* in_sizes, int n_in,
                              void* d_out, int out_size)
{
    const float* x       = (const float*)d_in[0];
    const int*   ei      = (const int*)  d_in[1];
    const float* in_fc_w = (const float*)d_in[2];
    const float* in_fc_b = (const float*)d_in[3];
    const float* w_rel   = (const float*)d_in[4];
    const float* b_rel   = (const float*)d_in[5];
    const float* w_root  = (const float*)d_in[6];

    int N = in_sizes[0] / D;
    int E = in_sizes[1] / 2;
    const int* src = ei;
    const int* dst = ei + E;

    float *H, *AGG;
    int *cnt, *row_ptr, *cursor, *adj;
    cudaGetSymbolAddress((void**)&H,       g_H);
    cudaGetSymbolAddress((void**)&AGG,     g_AGG);
    cudaGetSymbolAddress((void**)&cnt,     g_cnt);
    cudaGetSymbolAddress((void**)&row_ptr, g_row_ptr);
    cudaGetSymbolAddress((void**)&cursor,  g_cursor);
    cudaGetSymbolAddress((void**)&adj,     g_adj);

    int gblocks = (N + BM - 1) / BM;
    int eblocks = (E + 255) / 256;
    int ablocks = (N * 32 + 255) / 256;

    // ---- CSR build (dst-sorted adjacency) ----
    zero_int_kernel<<<(N + 255) / 256, 256>>>(cnt, N);
    hist_kernel<<<eblocks, 256>>>(dst, cnt, E);
    scan_kernel<<<1, 1024>>>(cnt, row_ptr, cursor, N);
    fill_kernel<<<eblocks, 256>>>(src, dst, cursor, adj, E);

    // ---- h = x @ in_fc_w + in_fc_b ----
    gemm_kernel<false><<<gblocks, 256>>>(x, in_fc_w, nullptr, nullptr,
                                         in_fc_b, nullptr, H, N);

    for (int l = 0; l < 3; l++) {
        aggregate_kernel<<<ablocks, 256>>>(H, row_ptr, adj, AGG, N);
        float* out_l = (l == 2) ? (float*)d_out : H;
        gemm_kernel<true><<<gblocks, 256>>>(AGG, w_rel + (size_t)l * D * D,
                                            H,   w_root + (size_t)l * D * D,
                                            b_rel + (size_t)l * D,
                                            H, out_l, N);
    }
}